// round 17
// baseline (speedup 1.0000x reference)
#include <cuda_runtime.h>
#include <cuda_fp16.h>
#include <math.h>
#include <stdint.h>

#define N_NODES 100000
#define N_EDGES 1600000
#define N_GRAPHS 256
#define D_HID 64
#define SCAN_BLOCKS 25   // ceil(100000/4096); 25 co-resident blocks -> chain is safe

// ---------------- scratch (device globals; no allocation allowed) ----------------
__device__ __align__(16) __half2 g_hh[(size_t)N_NODES * 32];    // h rows in fp16 (64 cols = 32 half2)
__device__ __align__(16) __half2 g_outh[(size_t)N_NODES * 32];  // layer-1 activated output (fp16)
__device__ __align__(16) float g_out[(size_t)N_NODES * D_HID];  // layer-2 output (fp32, for pooling)
__device__ float g_als[N_NODES];
__device__ float g_ald[N_NODES];
__device__ __align__(16) int g_cnt[N_NODES + 32]; // histogram (padded for int4 loads)
__device__ int   g_pack[N_EDGES];                 // dst | (rank<<17) per edge
__device__ int   g_rowptr[N_NODES + 1];
__device__ int   g_col[N_EDGES];                  // src node per CSR slot
__device__ int   g_chain[SCAN_BLOCKS];            // scan prefix chain (-1 = not ready)
__device__ float g_pool[N_GRAPHS * D_HID];
__device__ int   g_pcnt[N_GRAPHS];
__device__ int   g_shift;                         // 0: indices are int32, 1: int64

__device__ __forceinline__ int load_src(const int* p, int e, int sh) {
    return p[(size_t)e << sh];
}
__device__ __forceinline__ int load_dst(const int* p, int e, int sh) {
    return p[((size_t)N_EDGES + e) << sh];
}

// ---------------- zero + index dtype detection (fused) ----------------
__global__ void zero_all_kernel(const int* __restrict__ ei32) {
    int i = blockIdx.x * blockDim.x + threadIdx.x;
    if (i < N_NODES + 32) g_cnt[i] = 0;
    if (i < N_GRAPHS * D_HID) g_pool[i] = 0.f;
    if (i < N_GRAPHS) g_pcnt[i] = 0;
    if (i < SCAN_BLOCKS) g_chain[i] = -1;
    if (i == 0) {
        g_rowptr[N_NODES] = N_EDGES;
        int nz = 0;
#pragma unroll
        for (int k = 0; k < 16; k++) nz |= ei32[2 * k + 1];
        g_shift = (nz == 0) ? 1 : 0;
    }
}

// ---------------- CSR build ----------------
// count + per-edge rank in one pass; pack (dst, rank) into one int
__global__ void count_kernel(const int* __restrict__ ei) {
    int e = blockIdx.x * blockDim.x + threadIdx.x;
    int sh = g_shift;
    if (e < N_EDGES) {
        int d = load_dst(ei, e, sh);
        int r = atomicAdd(&g_cnt[d], 1);
        g_pack[e] = d | (r << 17);    // dst < 2^17, rank << 2^15
    }
}

// single-pass chained exclusive scan over g_cnt -> g_rowptr (4 elems/thread)
__global__ void scan_kernel() {
    __shared__ int sh[1024];
    __shared__ int carry;
    int bx = blockIdx.x;
    int tid = threadIdx.x;
    int i0 = bx * 4096 + tid * 4;
    int4 v4 = *reinterpret_cast<const int4*>(&g_cnt[i0]);   // padded; OOB region is zeros
    if (i0 >= N_NODES) { v4.x = v4.y = v4.z = v4.w = 0; }
    else {
        if (i0 + 1 >= N_NODES) v4.y = 0;
        if (i0 + 2 >= N_NODES) v4.z = 0;
        if (i0 + 3 >= N_NODES) v4.w = 0;
    }
    int p0 = 0, p1 = v4.x, p2 = v4.x + v4.y, p3 = v4.x + v4.y + v4.z;
    int tsum = p3 + v4.w;
    sh[tid] = tsum;
    __syncthreads();
#pragma unroll
    for (int off = 1; off < 1024; off <<= 1) {
        int t = (tid >= off) ? sh[tid - off] : 0;
        __syncthreads();
        sh[tid] += t;
        __syncthreads();
    }
    if (tid == 0) {
        int c = 0;
        if (bx > 0) {
            volatile int* ch = g_chain;
            while ((c = ch[bx - 1]) < 0) {}
        }
        ((volatile int*)g_chain)[bx] = c + sh[1023];
        carry = c;
    }
    __syncthreads();
    int base = carry + sh[tid] - tsum;                      // exclusive prefix of this thread
    if (i0 < N_NODES)     g_rowptr[i0]     = base + p0;
    if (i0 + 1 < N_NODES) g_rowptr[i0 + 1] = base + p1;
    if (i0 + 2 < N_NODES) g_rowptr[i0 + 2] = base + p2;
    if (i0 + 3 < N_NODES) g_rowptr[i0 + 3] = base + p3;
}

// no atomics: slot = rowptr[dst] + rank
__global__ void scatter_kernel(const int* __restrict__ ei) {
    int e = blockIdx.x * blockDim.x + threadIdx.x;
    int sh = g_shift;
    if (e < N_EDGES) {
        int v = g_pack[e];
        int d = v & 0x1FFFF;
        int r = v >> 17;
        g_col[g_rowptr[d] + r] = load_src(ei, e, sh);
    }
}

// ---------------- fused GEMM + attention-logit reduction ----------------
// h = X @ W  (K x 64) -> fp16 g_hh ; als = h . a_src, ald = h . a_dst (fp32 exact)
// 256 threads/block; each thread computes 4 nodes x 4 cols (register blocking).
// SRC: 0 = float X input, 1 = fp16 g_outh input (layer 2).
#define GNPB 64
template <int K, int SRC>
__global__ void __launch_bounds__(256) gemm_att_kernel(
    const float* __restrict__ X, const float* __restrict__ W,
    const float* __restrict__ avs, const float* __restrict__ avd)
{
    __shared__ __align__(16) float Ws[K * 64];
    __shared__ float Xs[GNPB * K];
    __shared__ float As[64], Ad[64];

    int tid = threadIdx.x;
    for (int idx = tid; idx < K * 64; idx += 256) Ws[idx] = W[idx];
    if (tid < 64) { As[tid] = avs[tid]; Ad[tid] = avd[tid]; }
    int nb = blockIdx.x * GNPB;
    if (SRC == 0) {
        int lim = GNPB * K;
        int base = nb * K;
        int maxe = N_NODES * K - base;
        for (int idx = tid; idx < lim; idx += 256)
            Xs[idx] = (idx < maxe) ? X[(size_t)base + idx] : 0.f;
    } else {
        const __half2* hp = g_outh;
        int lim = GNPB * K / 2;
        int base = nb * K / 2;
        int maxe = N_NODES * K / 2 - base;
        for (int idx = tid; idx < lim; idx += 256) {
            float2 f = (idx < maxe) ? __half22float2(hp[(size_t)base + idx])
                                    : make_float2(0.f, 0.f);
            Xs[2 * idx] = f.x;
            Xs[2 * idx + 1] = f.y;
        }
    }
    __syncthreads();

    int l16 = tid & 15;     // col group: cols l16*4 .. +3
    int ng = tid >> 4;      // node group: nodes nb + ng*4 .. +3

    float acc[4][4];
#pragma unroll
    for (int n = 0; n < 4; n++)
#pragma unroll
        for (int c = 0; c < 4; c++) acc[n][c] = 0.f;

    const float4* W4 = reinterpret_cast<const float4*>(Ws);
    const float* x0 = &Xs[(ng * 4 + 0) * K];
    const float* x1 = &Xs[(ng * 4 + 1) * K];
    const float* x2 = &Xs[(ng * 4 + 2) * K];
    const float* x3 = &Xs[(ng * 4 + 3) * K];
#pragma unroll 8
    for (int k = 0; k < K; k++) {
        float4 w = W4[k * 16 + l16];
        float xv0 = x0[k], xv1 = x1[k], xv2 = x2[k], xv3 = x3[k];
        acc[0][0] = fmaf(xv0, w.x, acc[0][0]);
        acc[0][1] = fmaf(xv0, w.y, acc[0][1]);
        acc[0][2] = fmaf(xv0, w.z, acc[0][2]);
        acc[0][3] = fmaf(xv0, w.w, acc[0][3]);
        acc[1][0] = fmaf(xv1, w.x, acc[1][0]);
        acc[1][1] = fmaf(xv1, w.y, acc[1][1]);
        acc[1][2] = fmaf(xv1, w.z, acc[1][2]);
        acc[1][3] = fmaf(xv1, w.w, acc[1][3]);
        acc[2][0] = fmaf(xv2, w.x, acc[2][0]);
        acc[2][1] = fmaf(xv2, w.y, acc[2][1]);
        acc[2][2] = fmaf(xv2, w.z, acc[2][2]);
        acc[2][3] = fmaf(xv2, w.w, acc[2][3]);
        acc[3][0] = fmaf(xv3, w.x, acc[3][0]);
        acc[3][1] = fmaf(xv3, w.y, acc[3][1]);
        acc[3][2] = fmaf(xv3, w.z, acc[3][2]);
        acc[3][3] = fmaf(xv3, w.w, acc[3][3]);
    }

    int c0 = l16 * 4;
    float as0 = As[c0], as1 = As[c0 + 1], as2 = As[c0 + 2], as3 = As[c0 + 3];
    float ad0 = Ad[c0], ad1 = Ad[c0 + 1], ad2 = Ad[c0 + 2], ad3 = Ad[c0 + 3];
#pragma unroll
    for (int n = 0; n < 4; n++) {
        int node = nb + ng * 4 + n;
        float ps = acc[n][0] * as0 + acc[n][1] * as1 + acc[n][2] * as2 + acc[n][3] * as3;
        float pd = acc[n][0] * ad0 + acc[n][1] * ad1 + acc[n][2] * ad2 + acc[n][3] * ad3;
#pragma unroll
        for (int off = 8; off; off >>= 1) {
            ps += __shfl_xor_sync(0xffffffffu, ps, off, 16);
            pd += __shfl_xor_sync(0xffffffffu, pd, off, 16);
        }
        if (node < N_NODES) {
            __half2 p0 = __floats2half2_rn(acc[n][0], acc[n][1]);
            __half2 p1 = __floats2half2_rn(acc[n][2], acc[n][3]);
            uint2 pk;
            pk.x = *reinterpret_cast<uint32_t*>(&p0);
            pk.y = *reinterpret_cast<uint32_t*>(&p1);
            *reinterpret_cast<uint2*>(&g_hh[(size_t)node * 32 + l16 * 2]) = pk;
            if (l16 == 0) { g_als[node] = ps; g_ald[node] = pd; }
        }
    }
}

// ---------------- fused softmax aggregation ----------------
// One warp per dst node. Gather phase: 8 lanes per edge x 4 edges in flight.
// Each lane owns a 16B slice (8 fp16 cols) of the row -> LDG.128, 8 fp32 accs.
// L1=true: apply leaky(0.01) and write fp16 g_outh; else write fp32 g_out.
// No max-subtraction: logits are O(+-25), fp32 expf is safe; softmax shift-invariant.
template <bool L1>
__global__ void __launch_bounds__(256) agg_kernel(const float* __restrict__ bias) {
    int i = (blockIdx.x * blockDim.x + threadIdx.x) >> 5;
    int lane = threadIdx.x & 31;
    if (i >= N_NODES) return;

    int grp = lane >> 3;          // 0..3  (edge slot)
    int slice = lane & 7;         // 0..7  (16B slice of the 128B row)
    const uint4* h4 = reinterpret_cast<const uint4*>(g_hh);

    float ald_i = g_ald[i];
    // self-loop (PyG GATConv adds them)
    float e0 = g_als[i] + ald_i;
    e0 = (e0 >= 0.f) ? e0 : 0.2f * e0;
    float w0 = __expf(e0);
    float ssum = (lane == 0) ? w0 : 0.f;

    float c0 = 0.f, c1 = 0.f, c2 = 0.f, c3 = 0.f, c4 = 0.f, c5 = 0.f, c6 = 0.f, c7 = 0.f;
    if (grp == 0) {  // group 0 contributes the self-loop once
        uint4 hv = h4[(size_t)i * 8 + slice];
        float2 f0 = __half22float2(*reinterpret_cast<__half2*>(&hv.x));
        float2 f1 = __half22float2(*reinterpret_cast<__half2*>(&hv.y));
        float2 f2 = __half22float2(*reinterpret_cast<__half2*>(&hv.z));
        float2 f3 = __half22float2(*reinterpret_cast<__half2*>(&hv.w));
        c0 = w0 * f0.x; c1 = w0 * f0.y; c2 = w0 * f1.x; c3 = w0 * f1.y;
        c4 = w0 * f2.x; c5 = w0 * f2.y; c6 = w0 * f3.x; c7 = w0 * f3.y;
    }

    int beg = g_rowptr[i], end = g_rowptr[i + 1];
    for (int j0 = beg; j0 < end; j0 += 32) {
        int cnt = end - j0;
        if (cnt > 32) cnt = 32;
        int src = 0;
        float w = 0.f;
        if (lane < cnt) {
            src = g_col[j0 + lane];
            float e = g_als[src] + ald_i;
            e = (e >= 0.f) ? e : 0.2f * e;
            w = __expf(e);
        }
        ssum += w;

        int iters = (cnt + 3) >> 2;       // warp-uniform
#pragma unroll 4
        for (int it = 0; it < iters; ++it) {
            int jj = it * 4 + grp;        // this group's edge within the chunk
            float wj = __shfl_sync(0xffffffffu, w, jj);
            int sj = __shfl_sync(0xffffffffu, src, jj);
            if (jj < cnt) {
                uint4 hv = h4[(size_t)sj * 8 + slice];
                float2 f0 = __half22float2(*reinterpret_cast<__half2*>(&hv.x));
                float2 f1 = __half22float2(*reinterpret_cast<__half2*>(&hv.y));
                float2 f2 = __half22float2(*reinterpret_cast<__half2*>(&hv.z));
                float2 f3 = __half22float2(*reinterpret_cast<__half2*>(&hv.w));
                c0 = fmaf(wj, f0.x, c0); c1 = fmaf(wj, f0.y, c1);
                c2 = fmaf(wj, f1.x, c2); c3 = fmaf(wj, f1.y, c3);
                c4 = fmaf(wj, f2.x, c4); c5 = fmaf(wj, f2.y, c5);
                c6 = fmaf(wj, f3.x, c6); c7 = fmaf(wj, f3.y, c7);
            }
        }
    }

    // cross-group reduction (lanes {l, l^8, l^16, l^24} hold the same columns)
#pragma unroll
    for (int off = 8; off <= 16; off <<= 1) {
        c0 += __shfl_xor_sync(0xffffffffu, c0, off);
        c1 += __shfl_xor_sync(0xffffffffu, c1, off);
        c2 += __shfl_xor_sync(0xffffffffu, c2, off);
        c3 += __shfl_xor_sync(0xffffffffu, c3, off);
        c4 += __shfl_xor_sync(0xffffffffu, c4, off);
        c5 += __shfl_xor_sync(0xffffffffu, c5, off);
        c6 += __shfl_xor_sync(0xffffffffu, c6, off);
        c7 += __shfl_xor_sync(0xffffffffu, c7, off);
    }
    // warp sum of weights
#pragma unroll
    for (int off = 16; off; off >>= 1)
        ssum += __shfl_xor_sync(0xffffffffu, ssum, off);

    if (grp == 0) {  // lanes 0..7 handle 8 columns each
        float inv = 1.f / (ssum + 1e-16f);
        const float4* b4 = reinterpret_cast<const float4*>(bias);
        float4 bA = b4[slice * 2];
        float4 bB = b4[slice * 2 + 1];
        float o0 = c0 * inv + bA.x, o1 = c1 * inv + bA.y;
        float o2 = c2 * inv + bA.z, o3 = c3 * inv + bA.w;
        float o4 = c4 * inv + bB.x, o5 = c5 * inv + bB.y;
        float o6 = c6 * inv + bB.z, o7 = c7 * inv + bB.w;
        if (L1) {
            o0 = (o0 >= 0.f) ? o0 : 0.01f * o0;
            o1 = (o1 >= 0.f) ? o1 : 0.01f * o1;
            o2 = (o2 >= 0.f) ? o2 : 0.01f * o2;
            o3 = (o3 >= 0.f) ? o3 : 0.01f * o3;
            o4 = (o4 >= 0.f) ? o4 : 0.01f * o4;
            o5 = (o5 >= 0.f) ? o5 : 0.01f * o5;
            o6 = (o6 >= 0.f) ? o6 : 0.01f * o6;
            o7 = (o7 >= 0.f) ? o7 : 0.01f * o7;
            __half2 q0 = __floats2half2_rn(o0, o1);
            __half2 q1 = __floats2half2_rn(o2, o3);
            __half2 q2 = __floats2half2_rn(o4, o5);
            __half2 q3 = __floats2half2_rn(o6, o7);
            uint4 pk;
            pk.x = *reinterpret_cast<uint32_t*>(&q0);
            pk.y = *reinterpret_cast<uint32_t*>(&q1);
            pk.z = *reinterpret_cast<uint32_t*>(&q2);
            pk.w = *reinterpret_cast<uint32_t*>(&q3);
            *reinterpret_cast<uint4*>(&g_outh[(size_t)i * 32 + slice * 4]) = pk;
        } else {
            float4* orow = reinterpret_cast<float4*>(&g_out[(size_t)i * 64 + slice * 8]);
            orow[0] = make_float4(o0, o1, o2, o3);
            orow[1] = make_float4(o4, o5, o6, o7);
        }
    }
}

// ---------------- pooling (batch is sorted -> segment-flush accumulation) ----------------
// 256 threads = 4 sub-chunks x 64 columns; each thread serially scans 64 nodes.
#define POOL_CH 256
__global__ void __launch_bounds__(256) pool_kernel(const int* __restrict__ batch) {
    __shared__ int bsh[POOL_CH];
    int start = blockIdx.x * POOL_CH;
    int lim = N_NODES - start;
    if (lim > POOL_CH) lim = POOL_CH;
    int t = threadIdx.x;
    int sh = g_shift;
    if (t < lim) bsh[t] = batch[(size_t)(start + t) << sh];
    __syncthreads();
    int c = t & 63;
    int sub = t >> 6;          // 0..3
    int s0 = sub * 64;
    int s1 = s0 + 64;
    if (s1 > lim) s1 = lim;
    if (s0 >= s1) return;
    int cur = bsh[s0];
    float acc = 0.f;
    int cnt = 0;
    for (int n = s0; n < s1; n++) {
        int b = bsh[n];
        if (b != cur) {
            atomicAdd(&g_pool[cur * 64 + c], acc);
            if (c == 0) atomicAdd(&g_pcnt[cur], cnt);
            acc = 0.f; cnt = 0; cur = b;
        }
        acc += g_out[(size_t)(start + n) * 64 + c];
        cnt++;
    }
    atomicAdd(&g_pool[cur * 64 + c], acc);
    if (c == 0) atomicAdd(&g_pcnt[cur], cnt);
}

// ---------------- final FC ----------------
__global__ void fc_kernel(const float* __restrict__ fcW, const float* __restrict__ fcb,
                          float* __restrict__ out) {
    int g = threadIdx.x;  // 256 graphs
    float cnt = fmaxf((float)g_pcnt[g], 1.f);
    float inv = 1.f / cnt;
    float o0 = fcb[0], o1 = fcb[1];
#pragma unroll
    for (int c = 0; c < 64; c++) {
        float p = g_pool[g * 64 + c] * inv;
        o0 = fmaf(p, fcW[2 * c], o0);
        o1 = fmaf(p, fcW[2 * c + 1], o1);
    }
    out[2 * g] = o0;
    out[2 * g + 1] = o1;
}

// ---------------- launch ----------------
extern "C" void kernel_launch(void* const* d_in, const int* in_sizes, int n_in,
                              void* d_out, int out_size) {
    const float* x      = (const float*)d_in[0];
    const int*   ei     = (const int*)d_in[1];    // int32 or int64 (detected on device)
    const int*   batch  = (const int*)d_in[2];
    const float* W1     = (const float*)d_in[3];
    const float* asrc1  = (const float*)d_in[4];
    const float* adst1  = (const float*)d_in[5];
    const float* b1     = (const float*)d_in[6];
    const float* W2     = (const float*)d_in[7];
    const float* asrc2  = (const float*)d_in[8];
    const float* adst2  = (const float*)d_in[9];
    const float* b2     = (const float*)d_in[10];
    const float* fcW    = (const float*)d_in[11];
    const float* fcb    = (const float*)d_in[12];
    float* out = (float*)d_out;

    // zero + dtype detect + CSR build (same graph used by both layers)
    zero_all_kernel<<<(N_NODES + 255) / 256, 256>>>(ei);
    count_kernel<<<(N_EDGES + 255) / 256, 256>>>(ei);
    scan_kernel<<<SCAN_BLOCKS, 1024>>>();
    scatter_kernel<<<(N_EDGES + 255) / 256, 256>>>(ei);

    // layer 1
    gemm_att_kernel<72, 0><<<(N_NODES + GNPB - 1) / GNPB, 256>>>(x, W1, asrc1, adst1);
    agg_kernel<true><<<(N_NODES * 32 + 255) / 256, 256>>>(b1);

    // layer 2 (input = fp16 g_outh from layer 1)
    gemm_att_kernel<64, 1><<<(N_NODES + GNPB - 1) / GNPB, 256>>>(nullptr, W2, asrc2, adst2);
    agg_kernel<false><<<(N_NODES * 32 + 255) / 256, 256>>>(b2);

    // pool + fc
    pool_kernel<<<(N_NODES + POOL_CH - 1) / POOL_CH, 256>>>(batch);
    fc_kernel<<<1, 256>>>(fcW, fcb, out);
}